// round 10
// baseline (speedup 1.0000x reference)
#include <cuda_runtime.h>
#include <math.h>

#define K_SEL 30
#define K_NRM 8
#define NWARPS 4
#define QPW 4                     // queries per warp
#define TILE 2048
#define FULL 0xFFFFFFFFu
#define NTHREADS (NWARPS * 32)

// Warp-collective slow path: insert the candidates flagged in `mask` into the
// warp-distributed sorted top-32 list `key` (lane i = rank i, 64-bit key =
// dist_bits<<32 | idx, exact lax.top_k tie-break). Handles mask==0 as no-op.
// thr_d is refreshed to lane-31's distance (warp-uniform).
__device__ __forceinline__ void topk_insert_masked(unsigned long long& key, float& thr_d,
                                                   unsigned mask, float d, unsigned idxval,
                                                   int lane) {
    if (mask) {                                        // warp-uniform
        const unsigned long long ck =
            ((unsigned long long)__float_as_uint(d) << 32) | idxval;
        unsigned long long thr = __shfl_sync(FULL, key, 31);
        do {
            const int src = __ffs(mask) - 1;
            mask &= mask - 1;
            const unsigned long long ins = __shfl_sync(FULL, ck, src);
            if (ins < thr) {   // exact (dist, idx) order, warp-uniform
                const unsigned lower = __ballot_sync(FULL, key < ins);
                const int pos = __popc(lower);
                const unsigned long long up = __shfl_up_sync(FULL, key, 1);
                if (lane > pos)       key = up;
                else if (lane == pos) key = ins;
                thr = __shfl_sync(FULL, key, 31);
            }
        } while (mask);
        thr_d = __uint_as_float((unsigned)(thr >> 32));
    }
}

// ---------------------------------------------------------------------------
// Single fused kernel.
// Phase 0: per-CTA compute of the 7x7 collapsed-attention matrix S
//          (S = (G Wq^T (+bq)) (G Wk^T (+bk))^T / sqrt(128); scores = y S y^T
//          with y=[pos_rel, normal_rel, 1] -- exact collapse, all ops affine).
// Phase 1: 4 queries per warp, exact 30-NN via warp-distributed sorted top-32
//          (float4 smem tile, 1-deep LDS prefetch pipeline).
// Phase 2: collapsed 7-dim attention epilogue per query.
// smem phases overlap via union; barriers separate them.
// ---------------------------------------------------------------------------
__global__ void __launch_bounds__(NTHREADS)
knn_attn_kernel(const float* __restrict__ x_world,
                const float* __restrict__ voxel_point,
                const float* __restrict__ voxel_normal,
                const float* __restrict__ v,
                const float* __restrict__ fc_w, const float* __restrict__ fc_b,
                const float* __restrict__ wq_w, const float* __restrict__ wq_b,
                const float* __restrict__ wk_w, const float* __restrict__ wk_b,
                float* __restrict__ out,
                int N, int M) {
    __shared__ union {
        struct {                               // phase 0: S computation scratch
            float G[7][128];
            float Hq[7][128];
            float Hk[7][128];
        } prep;
        float4 pts[TILE];                      // phase 1: candidate tile (32 KB)
        struct {                               // phase 2: epilogue scratch
            float z[NWARPS][K_SEL][7];
            float v[NWARPS][K_SEL];
        } epi;
    } sm;
    __shared__ float sS[49];

    const int tid  = threadIdx.x;
    const int warp = tid >> 5;
    const int lane = tid & 31;

    // ---------------- phase 0: compute S into sS ---------------------------
    {
        const int t = tid;   // 128 threads, one channel each
        #pragma unroll
        for (int j = 0; j < 6; ++j) sm.prep.G[j][t] = fc_w[t * 6 + j];
        sm.prep.G[6][t] = fc_b[t];
        __syncthreads();

        float aq[7] = {0,0,0,0,0,0,0};
        float ak[7] = {0,0,0,0,0,0,0};
        for (int c = 0; c < 128; ++c) {
            const float wq = wq_w[t * 128 + c];
            const float wk = wk_w[t * 128 + c];
            #pragma unroll
            for (int j = 0; j < 7; ++j) {
                aq[j] += sm.prep.G[j][c] * wq;
                ak[j] += sm.prep.G[j][c] * wk;
            }
        }
        aq[6] += wq_b[t];
        ak[6] += wk_b[t];
        #pragma unroll
        for (int j = 0; j < 7; ++j) { sm.prep.Hq[j][t] = aq[j]; sm.prep.Hk[j][t] = ak[j]; }
        __syncthreads();

        if (t < 49) {
            const int i = t / 7, j = t % 7;
            float s = 0.f;
            for (int d = 0; d < 128; ++d) s += sm.prep.Hq[i][d] * sm.prep.Hk[j][d];
            sS[t] = s * (1.0f / 11.313708498984760390f); // 1/sqrt(128)
        }
        // barrier before pts overlay is the first barrier of the tile loop
    }

    // ---------------- queries: 4 per warp, NaN for invalid -----------------
    const int q0 = (blockIdx.x * NWARPS + warp) * QPW;
    float qx[QPW], qy[QPW], qz[QPW];
    #pragma unroll
    for (int qi = 0; qi < QPW; ++qi) {
        const int q = q0 + qi;
        if (q < N) {
            qx[qi] = x_world[q * 3];
            qy[qi] = x_world[q * 3 + 1];
            qz[qi] = x_world[q * 3 + 2];
        } else {
            // NaN coords: every distance compares false -> zero inserts
            qx[qi] = qy[qi] = qz[qi] = __int_as_float(0x7FFFFFFF);
        }
    }

    unsigned long long key[QPW];
    float thr[QPW];
    #pragma unroll
    for (int qi = 0; qi < QPW; ++qi) {
        key[qi] = ((unsigned long long)0x7F800000u << 32) | 0xFFFFFFFFu; // (+inf, maxidx)
        thr[qi] = __int_as_float(0x7F800000);
    }

    // ---------------- phase 1: stream candidate tiles ----------------------
    const int ntiles = (M + TILE - 1) / TILE;
    for (int t = 0; t < ntiles; ++t) {
        const int base = t * TILE;
        __syncthreads();   // protect previous phase's readers
        if (base + TILE <= M) {
            // full tile: no per-element bounds test
            #pragma unroll 4
            for (int i = tid; i < TILE; i += NTHREADS) {
                const int g3 = (base + i) * 3;
                sm.pts[i] = make_float4(voxel_point[g3], voxel_point[g3 + 1],
                                        voxel_point[g3 + 2], 0.f);
            }
        } else {
            for (int i = tid; i < TILE; i += NTHREADS) {
                const int g = base + i;
                float x, y, z;
                if (g < M) {
                    x = voxel_point[g * 3];
                    y = voxel_point[g * 3 + 1];
                    z = voxel_point[g * 3 + 2];
                } else {
                    x = y = z = __int_as_float(0x7F800000); // +inf pad -> d=+inf
                }
                sm.pts[i] = make_float4(x, y, z, 0.f);
            }
        }
        __syncthreads();

        // 1-deep LDS prefetch pipeline: batch j+1's load issues before batch
        // j's processing, hiding the ~29cyc LDS latency at low occupancy.
        float4 p = sm.pts[lane];
        #pragma unroll 8
        for (int j = 0; j < TILE / 32; ++j) {
            const float4 pc = p;
            if (j + 1 < TILE / 32) p = sm.pts[(j + 1) * 32 + lane];

            float d[QPW];
            #pragma unroll
            for (int qi = 0; qi < QPW; ++qi) {
                const float dx = qx[qi] - pc.x;
                const float dy = qy[qi] - pc.y;
                const float dz = qz[qi] - pc.z;
                d[qi] = fmaf(dx, dx, fmaf(dy, dy, dz * dz));
            }
            unsigned m[QPW];
            #pragma unroll
            for (int qi = 0; qi < QPW; ++qi)
                m[qi] = __ballot_sync(FULL, d[qi] <= thr[qi]); // conservative superset

            if ((m[0] | m[1]) | (m[2] | m[3])) {   // warp-uniform
                const unsigned gidx = (unsigned)(base + j * 32 + lane); // slow path only
                #pragma unroll
                for (int qi = 0; qi < QPW; ++qi)
                    topk_insert_masked(key[qi], thr[qi], m[qi], d[qi], gidx, lane);
            }
        }
    }

    // barrier before overlaying epilogue scratch on the tile buffer
    __syncthreads();

    // ---------------- phase 2: collapsed attention, per query --------------
    #pragma unroll
    for (int qi = 0; qi < QPW; ++qi) {
        const int q = q0 + qi;
        if (q >= N) break;   // warp-uniform
        const unsigned idx = (unsigned)(key[qi] & 0xFFFFFFFFull);
        const bool act = (lane < K_SEL);

        float vnx = 0.f, vny = 0.f, vnz = 0.f;
        if (act) {
            vnx = voxel_normal[idx * 3];
            vny = voxel_normal[idx * 3 + 1];
            vnz = voxel_normal[idx * 3 + 2];
        }
        // x_normal = mean of 8 nearest normals
        float sx = (lane < K_NRM) ? vnx : 0.f;
        float sy = (lane < K_NRM) ? vny : 0.f;
        float sz = (lane < K_NRM) ? vnz : 0.f;
        #pragma unroll
        for (int o = 16; o > 0; o >>= 1) {
            sx += __shfl_xor_sync(FULL, sx, o);
            sy += __shfl_xor_sync(FULL, sy, o);
            sz += __shfl_xor_sync(FULL, sz, o);
        }
        sx *= 0.125f; sy *= 0.125f; sz *= 0.125f;

        float y[7];
        if (act) {
            const float px = voxel_point[idx * 3];
            const float py = voxel_point[idx * 3 + 1];
            const float pz = voxel_point[idx * 3 + 2];
            y[0] = qx[qi] - px; y[1] = qy[qi] - py; y[2] = qz[qi] - pz;
            y[3] = sx - vnx; y[4] = sy - vny; y[5] = sz - vnz;
            y[6] = 1.f;
            #pragma unroll
            for (int i = 0; i < 7; ++i) {
                float acc = 0.f;
                #pragma unroll
                for (int jj = 0; jj < 7; ++jj) acc += sS[i * 7 + jj] * y[jj];
                sm.epi.z[warp][lane][i] = acc;   // z_l = S y_l
            }
            sm.epi.v[warp][lane] = v[idx];
        }
        __syncwarp(FULL);

        float outk = 0.f;
        if (act) {
            // online softmax over l: score[k][l] = y_k . z_l
            float mmax = __int_as_float(0xFF800000); // -inf
            float se = 0.f, sv = 0.f;
            for (int l = 0; l < K_SEL; ++l) {
                float s = 0.f;
                #pragma unroll
                for (int i = 0; i < 7; ++i) s += y[i] * sm.epi.z[warp][l][i];
                const float mn = fmaxf(mmax, s);
                const float corr = __expf(mmax - mn);
                const float e = __expf(s - mn);
                se = se * corr + e;
                sv = sv * corr + e * sm.epi.v[warp][l];
                mmax = mn;
            }
            outk = sv / se;
        }
        float tot = act ? outk : 0.f;
        #pragma unroll
        for (int o = 16; o > 0; o >>= 1) tot += __shfl_xor_sync(FULL, tot, o);
        if (lane == 0) out[q] = tot * (1.0f / 30.0f);
        __syncwarp(FULL);   // epi scratch reused by next qi
    }
}

// ---------------------------------------------------------------------------
extern "C" void kernel_launch(void* const* d_in, const int* in_sizes, int n_in,
                              void* d_out, int out_size) {
    const float* x_world      = (const float*)d_in[0];
    const float* voxel_point  = (const float*)d_in[1];
    const float* voxel_normal = (const float*)d_in[2];
    const float* v            = (const float*)d_in[3];
    const float* fc_w         = (const float*)d_in[4];
    const float* fc_b         = (const float*)d_in[5];
    const float* wq_w         = (const float*)d_in[6];
    const float* wq_b         = (const float*)d_in[7];
    const float* wk_w         = (const float*)d_in[8];
    const float* wk_b         = (const float*)d_in[9];
    float* out = (float*)d_out;

    const int N = in_sizes[0] / 3;
    const int M = in_sizes[1] / 3;

    const int qpb = NWARPS * QPW;
    const int blocks = (N + qpb - 1) / qpb;
    knn_attn_kernel<<<blocks, NTHREADS>>>(x_world, voxel_point, voxel_normal, v,
                                          fc_w, fc_b, wq_w, wq_b, wk_w, wk_b,
                                          out, N, M);
}

// round 12
// speedup vs baseline: 1.1226x; 1.1226x over previous
#include <cuda_runtime.h>
#include <math.h>

#define K_SEL 30
#define K_NRM 8
#define NWARPS 8
#define QPW 2                     // queries per warp
#define TILE 2048
#define FULL 0xFFFFFFFFu
#define NTHREADS (NWARPS * 32)

// Warp-collective slow path: insert the candidates flagged in `mask` into the
// warp-distributed sorted top-32 list `key` (lane i = rank i, 64-bit key =
// dist_bits<<32 | idx, exact lax.top_k tie-break). Handles mask==0 as no-op.
// thr_d is refreshed to lane-31's distance (warp-uniform).
__device__ __forceinline__ void topk_insert_masked(unsigned long long& key, float& thr_d,
                                                   unsigned mask, float d, unsigned idxval,
                                                   int lane) {
    if (mask) {                                        // warp-uniform
        const unsigned long long ck =
            ((unsigned long long)__float_as_uint(d) << 32) | idxval;
        unsigned long long thr = __shfl_sync(FULL, key, 31);
        do {
            const int src = __ffs(mask) - 1;
            mask &= mask - 1;
            const unsigned long long ins = __shfl_sync(FULL, ck, src);
            if (ins < thr) {   // exact (dist, idx) order, warp-uniform
                const unsigned lower = __ballot_sync(FULL, key < ins);
                const int pos = __popc(lower);
                const unsigned long long up = __shfl_up_sync(FULL, key, 1);
                if (lane > pos)       key = up;
                else if (lane == pos) key = ins;
                thr = __shfl_sync(FULL, key, 31);
            }
        } while (mask);
        thr_d = __uint_as_float((unsigned)(thr >> 32));
    }
}

// ---------------------------------------------------------------------------
// Single fused kernel, R7 occupancy shape (8 warps x 2 queries) + float4 tile.
// Phase 0: per-CTA compute of the 7x7 collapsed-attention matrix S
//          (S = (G Wq^T (+bq)) (G Wk^T (+bk))^T / sqrt(128); scores = y S y^T
//          with y=[pos_rel, normal_rel, 1] -- exact collapse, all ops affine).
// Phase 1: 2 queries per warp, exact 30-NN via warp-distributed sorted top-32
//          (float4 smem tile: one LDS.128 per candidate batch, 1-deep prefetch).
// Phase 2: collapsed 7-dim attention epilogue per query.
// smem phases overlap via union; barriers separate them.
// ---------------------------------------------------------------------------
__global__ void __launch_bounds__(NTHREADS)
knn_attn_kernel(const float* __restrict__ x_world,
                const float* __restrict__ voxel_point,
                const float* __restrict__ voxel_normal,
                const float* __restrict__ v,
                const float* __restrict__ fc_w, const float* __restrict__ fc_b,
                const float* __restrict__ wq_w, const float* __restrict__ wq_b,
                const float* __restrict__ wk_w, const float* __restrict__ wk_b,
                float* __restrict__ out,
                int N, int M) {
    __shared__ union {
        struct {                               // phase 0: S computation scratch
            float G[7][128];
            float Hq[7][128];
            float Hk[7][128];
        } prep;
        float4 pts[TILE];                      // phase 1: candidate tile (32 KB)
        struct {                               // phase 2: epilogue scratch
            float z[NWARPS][K_SEL][7];
            float v[NWARPS][K_SEL];
        } epi;
    } sm;
    __shared__ float sS[49];

    const int tid  = threadIdx.x;
    const int warp = tid >> 5;
    const int lane = tid & 31;

    // ---------------- phase 0: compute S into sS ---------------------------
    if (tid < 128) {
        #pragma unroll
        for (int j = 0; j < 6; ++j) sm.prep.G[j][tid] = fc_w[tid * 6 + j];
        sm.prep.G[6][tid] = fc_b[tid];
    }
    __syncthreads();
    if (tid < 128) {
        float aq[7] = {0,0,0,0,0,0,0};
        float ak[7] = {0,0,0,0,0,0,0};
        for (int c = 0; c < 128; ++c) {
            const float wq = wq_w[tid * 128 + c];
            const float wk = wk_w[tid * 128 + c];
            #pragma unroll
            for (int j = 0; j < 7; ++j) {
                aq[j] += sm.prep.G[j][c] * wq;
                ak[j] += sm.prep.G[j][c] * wk;
            }
        }
        aq[6] += wq_b[tid];
        ak[6] += wk_b[tid];
        #pragma unroll
        for (int j = 0; j < 7; ++j) { sm.prep.Hq[j][tid] = aq[j]; sm.prep.Hk[j][tid] = ak[j]; }
    }
    __syncthreads();
    if (tid < 49) {
        const int i = tid / 7, j = tid % 7;
        float s = 0.f;
        for (int d = 0; d < 128; ++d) s += sm.prep.Hq[i][d] * sm.prep.Hk[j][d];
        sS[tid] = s * (1.0f / 11.313708498984760390f); // 1/sqrt(128)
    }
    // barrier before pts overlay is the first barrier of the tile loop

    // ---------------- queries: 2 per warp, NaN for invalid -----------------
    const int q0 = (blockIdx.x * NWARPS + warp) * QPW;
    float qx[QPW], qy[QPW], qz[QPW];
    #pragma unroll
    for (int qi = 0; qi < QPW; ++qi) {
        const int q = q0 + qi;
        if (q < N) {
            qx[qi] = x_world[q * 3];
            qy[qi] = x_world[q * 3 + 1];
            qz[qi] = x_world[q * 3 + 2];
        } else {
            // NaN coords: every distance compares false -> zero inserts
            qx[qi] = qy[qi] = qz[qi] = __int_as_float(0x7FFFFFFF);
        }
    }

    unsigned long long key[QPW];
    float thr[QPW];
    #pragma unroll
    for (int qi = 0; qi < QPW; ++qi) {
        key[qi] = ((unsigned long long)0x7F800000u << 32) | 0xFFFFFFFFu; // (+inf, maxidx)
        thr[qi] = __int_as_float(0x7F800000);
    }

    // ---------------- phase 1: stream candidate tiles ----------------------
    const int ntiles = (M + TILE - 1) / TILE;
    for (int t = 0; t < ntiles; ++t) {
        const int base = t * TILE;
        __syncthreads();   // protect previous phase's readers
        if (base + TILE <= M) {
            // full tile: no per-element bounds test
            #pragma unroll 4
            for (int i = tid; i < TILE; i += NTHREADS) {
                const int g3 = (base + i) * 3;
                sm.pts[i] = make_float4(voxel_point[g3], voxel_point[g3 + 1],
                                        voxel_point[g3 + 2], 0.f);
            }
        } else {
            for (int i = tid; i < TILE; i += NTHREADS) {
                const int g = base + i;
                float x, y, z;
                if (g < M) {
                    x = voxel_point[g * 3];
                    y = voxel_point[g * 3 + 1];
                    z = voxel_point[g * 3 + 2];
                } else {
                    x = y = z = __int_as_float(0x7F800000); // +inf pad -> d=+inf
                }
                sm.pts[i] = make_float4(x, y, z, 0.f);
            }
        }
        __syncthreads();

        // 1-deep LDS prefetch pipeline
        float4 p = sm.pts[lane];
        #pragma unroll 8
        for (int j = 0; j < TILE / 32; ++j) {
            const float4 pc = p;
            if (j + 1 < TILE / 32) p = sm.pts[(j + 1) * 32 + lane];

            float d[QPW];
            #pragma unroll
            for (int qi = 0; qi < QPW; ++qi) {
                const float dx = qx[qi] - pc.x;
                const float dy = qy[qi] - pc.y;
                const float dz = qz[qi] - pc.z;
                d[qi] = fmaf(dx, dx, fmaf(dy, dy, dz * dz));
            }
            unsigned m[QPW];
            #pragma unroll
            for (int qi = 0; qi < QPW; ++qi)
                m[qi] = __ballot_sync(FULL, d[qi] <= thr[qi]); // conservative superset

            if (m[0] | m[1]) {   // warp-uniform, rare after warm-up
                const unsigned gidx = (unsigned)(base + j * 32 + lane); // slow path only
                #pragma unroll
                for (int qi = 0; qi < QPW; ++qi)
                    topk_insert_masked(key[qi], thr[qi], m[qi], d[qi], gidx, lane);
            }
        }
    }

    // barrier before overlaying epilogue scratch on the tile buffer
    __syncthreads();

    // ---------------- phase 2: collapsed attention, per query --------------
    #pragma unroll
    for (int qi = 0; qi < QPW; ++qi) {
        const int q = q0 + qi;
        if (q >= N) break;   // warp-uniform
        const unsigned idx = (unsigned)(key[qi] & 0xFFFFFFFFull);
        const bool act = (lane < K_SEL);

        float vnx = 0.f, vny = 0.f, vnz = 0.f;
        if (act) {
            vnx = voxel_normal[idx * 3];
            vny = voxel_normal[idx * 3 + 1];
            vnz = voxel_normal[idx * 3 + 2];
        }
        // x_normal = mean of 8 nearest normals
        float sx = (lane < K_NRM) ? vnx : 0.f;
        float sy = (lane < K_NRM) ? vny : 0.f;
        float sz = (lane < K_NRM) ? vnz : 0.f;
        #pragma unroll
        for (int o = 16; o > 0; o >>= 1) {
            sx += __shfl_xor_sync(FULL, sx, o);
            sy += __shfl_xor_sync(FULL, sy, o);
            sz += __shfl_xor_sync(FULL, sz, o);
        }
        sx *= 0.125f; sy *= 0.125f; sz *= 0.125f;

        float y[7];
        if (act) {
            const float px = voxel_point[idx * 3];
            const float py = voxel_point[idx * 3 + 1];
            const float pz = voxel_point[idx * 3 + 2];
            y[0] = qx[qi] - px; y[1] = qy[qi] - py; y[2] = qz[qi] - pz;
            y[3] = sx - vnx; y[4] = sy - vny; y[5] = sz - vnz;
            y[6] = 1.f;
            #pragma unroll
            for (int i = 0; i < 7; ++i) {
                float acc = 0.f;
                #pragma unroll
                for (int jj = 0; jj < 7; ++jj) acc += sS[i * 7 + jj] * y[jj];
                sm.epi.z[warp][lane][i] = acc;   // z_l = S y_l
            }
            sm.epi.v[warp][lane] = v[idx];
        }
        __syncwarp(FULL);

        float outk = 0.f;
        if (act) {
            // online softmax over l: score[k][l] = y_k . z_l
            float mmax = __int_as_float(0xFF800000); // -inf
            float se = 0.f, sv = 0.f;
            for (int l = 0; l < K_SEL; ++l) {
                float s = 0.f;
                #pragma unroll
                for (int i = 0; i < 7; ++i) s += y[i] * sm.epi.z[warp][l][i];
                const float mn = fmaxf(mmax, s);
                const float corr = __expf(mmax - mn);
                const float e = __expf(s - mn);
                se = se * corr + e;
                sv = sv * corr + e * sm.epi.v[warp][l];
                mmax = mn;
            }
            outk = sv / se;
        }
        float tot = act ? outk : 0.f;
        #pragma unroll
        for (int o = 16; o > 0; o >>= 1) tot += __shfl_xor_sync(FULL, tot, o);
        if (lane == 0) out[q] = tot * (1.0f / 30.0f);
        __syncwarp(FULL);   // epi scratch reused by next qi
    }
}

// ---------------------------------------------------------------------------
extern "C" void kernel_launch(void* const* d_in, const int* in_sizes, int n_in,
                              void* d_out, int out_size) {
    const float* x_world      = (const float*)d_in[0];
    const float* voxel_point  = (const float*)d_in[1];
    const float* voxel_normal = (const float*)d_in[2];
    const float* v            = (const float*)d_in[3];
    const float* fc_w         = (const float*)d_in[4];
    const float* fc_b         = (const float*)d_in[5];
    const float* wq_w         = (const float*)d_in[6];
    const float* wq_b         = (const float*)d_in[7];
    const float* wk_w         = (const float*)d_in[8];
    const float* wk_b         = (const float*)d_in[9];
    float* out = (float*)d_out;

    const int N = in_sizes[0] / 3;
    const int M = in_sizes[1] / 3;

    const int qpb = NWARPS * QPW;
    const int blocks = (N + qpb - 1) / qpb;
    knn_attn_kernel<<<blocks, NTHREADS>>>(x_world, voxel_point, voxel_normal, v,
                                          fc_w, fc_b, wq_w, wq_b, wk_w, wk_b,
                                          out, N, M);
}